// round 15
// baseline (speedup 1.0000x reference)
#include <cuda_runtime.h>
#include <cuda_fp16.h>
#include <math.h>
#include <stdint.h>

#define B_  16
#define S_  1024
#define E_  1024
#define F_  4096
#define H_  16
#define D_  64
#define M_  (B_*S_)   // 16384 rows

// ---------------- scratch (device globals: allocation-free) ----------------
__device__ __half g_xn [(size_t)M_*E_];     //  32 MB  layernorm output (fp16)
__device__ __half g_qkv[(size_t)M_*3*E_];   //  96 MB  qkv projection (fp16)
__device__ __half g_ctx[(size_t)M_*E_];     //  32 MB  attention context (fp16)
__device__ float  g_x1 [(size_t)M_*E_];     //  64 MB  post-attention residual (fp32)
__device__ __half g_h  [(size_t)M_*F_];     // 128 MB  ffn hidden (fp16)
__device__ __half g_w  [12582912];          //  24 MB  fp16 weights

#define WOFF_IN   0
#define WOFF_OUT  3145728
#define WOFF_L1   4194304
#define WOFF_L2   8388608

// ---------------- helpers ----------------
__device__ __forceinline__ void mma_f16(float c[4], const unsigned a[4], const unsigned b[2]) {
    asm volatile(
        "mma.sync.aligned.m16n8k16.row.col.f32.f16.f16.f32 "
        "{%0,%1,%2,%3}, {%4,%5,%6,%7}, {%8,%9}, {%0,%1,%2,%3};\n"
        : "+f"(c[0]), "+f"(c[1]), "+f"(c[2]), "+f"(c[3])
        : "r"(a[0]), "r"(a[1]), "r"(a[2]), "r"(a[3]), "r"(b[0]), "r"(b[1]));
}
__device__ __forceinline__ void ldsm_x4(unsigned &r0, unsigned &r1, unsigned &r2, unsigned &r3, uint32_t a) {
    asm volatile("ldmatrix.sync.aligned.m8n8.x4.shared.b16 {%0,%1,%2,%3}, [%4];"
                 : "=r"(r0), "=r"(r1), "=r"(r2), "=r"(r3) : "r"(a));
}
__device__ __forceinline__ void ldsm_x4_t(unsigned &r0, unsigned &r1, unsigned &r2, unsigned &r3, uint32_t a) {
    asm volatile("ldmatrix.sync.aligned.m8n8.x4.trans.shared.b16 {%0,%1,%2,%3}, [%4];"
                 : "=r"(r0), "=r"(r1), "=r"(r2), "=r"(r3) : "r"(a));
}
__device__ __forceinline__ uint32_t smem_u32(const void* p) {
    uint32_t a;
    asm("{ .reg .u64 t; cvta.to.shared.u64 t, %1; cvt.u32.u64 %0, t; }" : "=r"(a) : "l"(p));
    return a;
}
__device__ __forceinline__ void cp_async16(unsigned dst, const void* src) {
    asm volatile("cp.async.cg.shared.global [%0], [%1], 16;\n" :: "r"(dst), "l"(src));
}
__device__ __forceinline__ unsigned pack_h2(float a, float b) {
    __half2 h = __floats2half2_rn(a, b);
    return *(unsigned*)&h;
}
__device__ __forceinline__ unsigned ex2_h2(unsigned x) {
    unsigned y;
    asm("ex2.approx.f16x2 %0, %1;" : "=r"(y) : "r"(x));
    return y;
}
__device__ __forceinline__ unsigned hadd2u(unsigned a, unsigned b) {
    __half2 r = __hadd2(*(__half2*)&a, *(__half2*)&b);
    return *(unsigned*)&r;
}
__device__ __forceinline__ float tanhf_apx(float x) {
    float y;
    asm("tanh.approx.f32 %0, %1;" : "=f"(y) : "f"(x));
    return y;
}
__device__ __forceinline__ float gelu_f(float x) {
    float inner = 0.7978845608028654f * (x + 0.044715f * x * x * x);
    return 0.5f * x * (1.0f + tanhf_apx(inner));
}

// ---------------- fused fp32 -> fp16 weight convert (all 4 weights) ---------
__global__ __launch_bounds__(256) void cvt_all(
    const float* __restrict__ s0, const float* __restrict__ s1,
    const float* __restrict__ s2, const float* __restrict__ s3,
    __half* __restrict__ dst)
{
    int c = blockIdx.x * 256 + threadIdx.x;   // chunk of 8 elements
    const float* src; size_t off;
    if (c < 393216)       { src = s0; off = (size_t)c * 8; }
    else if (c < 524288)  { src = s1; off = (size_t)(c - 393216) * 8; }
    else if (c < 1048576) { src = s2; off = (size_t)(c - 524288) * 8; }
    else                  { src = s3; off = (size_t)(c - 1048576) * 8; }
    float4 a = *(const float4*)(src + off);
    float4 b = *(const float4*)(src + off + 4);
    __half2 h[4];
    h[0] = __floats2half2_rn(a.x, a.y);
    h[1] = __floats2half2_rn(a.z, a.w);
    h[2] = __floats2half2_rn(b.x, b.y);
    h[3] = __floats2half2_rn(b.z, b.w);
    ((uint4*)dst)[c] = *(uint4*)h;
}

// ---------------- layernorm: warp-per-row, 8 rows per 256-thread block ------
__global__ __launch_bounds__(256) void ln_kernel(
    const float* __restrict__ x, const float* __restrict__ w,
    const float* __restrict__ b, __half* __restrict__ y)
{
    int warp = threadIdx.x >> 5, lane = threadIdx.x & 31;
    int row  = blockIdx.x * 8 + warp;
    const float4* xr = (const float4*)(x + (size_t)row * E_);

    float4 v[8];
    #pragma unroll
    for (int i = 0; i < 8; i++) v[i] = xr[lane + i * 32];

    float s = 0.f, q = 0.f;
    #pragma unroll
    for (int i = 0; i < 8; i++) {
        s += v[i].x + v[i].y + v[i].z + v[i].w;
        q += v[i].x*v[i].x + v[i].y*v[i].y + v[i].z*v[i].z + v[i].w*v[i].w;
    }
    #pragma unroll
    for (int o = 16; o; o >>= 1) {
        s += __shfl_xor_sync(0xffffffffu, s, o);
        q += __shfl_xor_sync(0xffffffffu, q, o);
    }
    float mu  = s * (1.0f / E_);
    float var = q * (1.0f / E_) - mu * mu;
    float inv = rsqrtf(var + 1e-5f);

    uint4* yr = (uint4*)(y + (size_t)row * E_);
    #pragma unroll
    for (int i = 0; i < 8; i += 2) {
        float4 wv0 = ((const float4*)w)[lane + i * 32];
        float4 bv0 = ((const float4*)b)[lane + i * 32];
        float4 wv1 = ((const float4*)w)[lane + (i + 1) * 32];
        float4 bv1 = ((const float4*)b)[lane + (i + 1) * 32];
        __half2 h0 = __floats2half2_rn((v[i].x - mu) * inv * wv0.x + bv0.x,
                                       (v[i].y - mu) * inv * wv0.y + bv0.y);
        __half2 h1 = __floats2half2_rn((v[i].z - mu) * inv * wv0.z + bv0.z,
                                       (v[i].w - mu) * inv * wv0.w + bv0.w);
        __half2 h2 = __floats2half2_rn((v[i+1].x - mu) * inv * wv1.x + bv1.x,
                                       (v[i+1].y - mu) * inv * wv1.y + bv1.y);
        __half2 h3 = __floats2half2_rn((v[i+1].z - mu) * inv * wv1.z + bv1.z,
                                       (v[i+1].w - mu) * inv * wv1.w + bv1.w);
        uint2 u0; u0.x = *(unsigned*)&h0; u0.y = *(unsigned*)&h1;
        uint2 u1; u1.x = *(unsigned*)&h2; u1.y = *(unsigned*)&h3;
        ((uint2*)yr)[lane + i * 32]       = u0;
        ((uint2*)yr)[lane + (i + 1) * 32] = u1;
    }
}

// ---------------- persistent fp16 NT GEMM: C = A @ B^T (+bias, epi) ---------
// EPI: 0 = bias -> half, 1 = bias + gelu(tanh) -> half, 2 = bias + residual -> float
#define RSB   144                 // row stride bytes (128B data + 16B pad)
#define ABYT  (128*RSB)           // 18432 bytes per tile
#define STB   (2*ABYT)            // 36864 bytes per stage
#define NST   3
#define GSM   (NST*STB)           // 110592 bytes
#define NPERS 304                 // 2 CTAs x 152 SMs

template<int EPI>
__global__ __launch_bounds__(256, 2) void gemm_h(
    const __half* __restrict__ A, const __half* __restrict__ Bm,
    const float* __restrict__ bias, const float* __restrict__ res,
    void* __restrict__ Cv, int N, int K, int ntiles)
{
    extern __shared__ char smh[];
    uint32_t sb = smem_u32(smh);
    int tid = threadIdx.x;
    int w = tid >> 5, lane = tid & 31, g = lane >> 2, t = lane & 3;
    int wm = (w >> 1) * 32, wn = (w & 1) * 64;
    int srow = tid >> 3, sq = tid & 7;
    uint32_t sA = srow * RSB + sq * 16;
    uint32_t sB = ABYT + sA;
    int arow = lane & 15;
    int akof = (lane >> 4) * 16;
    int brow = (lane & 7) + ((lane >> 4) << 3);
    int bkof = ((lane >> 3) & 1) * 16;
    int NT = N >> 7;
    int KT = K / 64;

    for (int tile = blockIdx.x; tile < ntiles; tile += NPERS) {
        int bn = (tile % NT) << 7;
        int bm = (tile / NT) << 7;
        const __half* gA = A  + (size_t)(bm + srow) * K + sq * 8;
        const __half* gB = Bm + (size_t)(bn + srow) * K + sq * 8;

        asm volatile("cp.async.wait_group 0;\n");
        __syncthreads();

        #pragma unroll
        for (int s = 0; s < 2; s++) {
            uint32_t stb = sb + s * STB;
            #pragma unroll
            for (int u = 0; u < 4; u++) {
                cp_async16(stb + sA + u * 32 * RSB, gA + (size_t)u * 32 * K + s * 64);
                cp_async16(stb + sB + u * 32 * RSB, gB + (size_t)u * 32 * K + s * 64);
            }
            asm volatile("cp.async.commit_group;\n");
        }

        float acc[2][8][4];
        #pragma unroll
        for (int i = 0; i < 2; i++)
            #pragma unroll
            for (int j = 0; j < 8; j++)
                #pragma unroll
                for (int k = 0; k < 4; k++) acc[i][j][k] = 0.f;

        int buf = 0;
        for (int kt = 0; kt < KT; kt++) {
            asm volatile("cp.async.wait_group 1;\n");
            __syncthreads();

            bool pf = (kt + 2 < KT);
            int nb = buf + 2; if (nb >= NST) nb -= NST;
            uint32_t stb = sb + nb * STB;
            int k0 = (kt + 2) * 64;

            uint32_t abase = sb + buf * STB + (wm + arow) * RSB + akof;
            uint32_t bbase = sb + buf * STB + ABYT + (wn + brow) * RSB + bkof;

            #pragma unroll
            for (int ks = 0; ks < 4; ks++) {
                if (pf) {
                    cp_async16(stb + sA + ks * 32 * RSB, gA + (size_t)ks * 32 * K + k0);
                    cp_async16(stb + sB + ks * 32 * RSB, gB + (size_t)ks * 32 * K + k0);
                }
                unsigned af[2][4], bf[8][2];
                #pragma unroll
                for (int mf = 0; mf < 2; mf++)
                    ldsm_x4(af[mf][0], af[mf][1], af[mf][2], af[mf][3],
                            abase + mf * 16 * RSB + ks * 32);
                #pragma unroll
                for (int p = 0; p < 4; p++) {
                    unsigned r0, r1, r2, r3;
                    ldsm_x4(r0, r1, r2, r3, bbase + p * 16 * RSB + ks * 32);
                    bf[2*p][0] = r0; bf[2*p][1] = r1;
                    bf[2*p+1][0] = r2; bf[2*p+1][1] = r3;
                }
                #pragma unroll
                for (int mf = 0; mf < 2; mf++)
                    #pragma unroll
                    for (int nf = 0; nf < 8; nf++)
                        mma_f16(acc[mf][nf], af[mf], bf[nf]);
            }
            asm volatile("cp.async.commit_group;\n");
            if (++buf == NST) buf = 0;
        }

        #pragma unroll
        for (int mf = 0; mf < 2; mf++) {
            size_t r0 = (size_t)(bm + wm + mf * 16 + g);
            float2 rs0[8], rs1[8];
            if (EPI == 2) {
                #pragma unroll
                for (int nf = 0; nf < 8; nf++) {
                    int c0 = bn + wn + nf * 8 + 2 * t;
                    rs0[nf] = *(const float2*)(res + r0 * N + c0);
                    rs1[nf] = *(const float2*)(res + (r0 + 8) * N + c0);
                }
            }
            #pragma unroll
            for (int nf = 0; nf < 8; nf++) {
                int c0 = bn + wn + nf * 8 + 2 * t;
                float b0 = bias[c0], b1 = bias[c0 + 1];
                float v0 = acc[mf][nf][0] + b0;
                float v1 = acc[mf][nf][1] + b1;
                float v2 = acc[mf][nf][2] + b0;
                float v3 = acc[mf][nf][3] + b1;
                if (EPI == 1) {
                    v0 = gelu_f(v0);
                    v1 = gelu_f(v1);
                    v2 = gelu_f(v2);
                    v3 = gelu_f(v3);
                }
                if (EPI == 2) {
                    float* C = (float*)Cv;
                    float2 o01; o01.x = v0 + rs0[nf].x; o01.y = v1 + rs0[nf].y;
                    float2 o23; o23.x = v2 + rs1[nf].x; o23.y = v3 + rs1[nf].y;
                    *(float2*)(C + r0 * N + c0)       = o01;
                    *(float2*)(C + (r0 + 8) * N + c0) = o23;
                } else {
                    __half* C = (__half*)Cv;
                    *(__half2*)(C + r0 * N + c0)       = __floats2half2_rn(v0, v1);
                    *(__half2*)(C + (r0 + 8) * N + c0) = __floats2half2_rn(v2, v3);
                }
            }
        }
    }
}

// ---------------- fp16 flash attention v2: kv-tile 128, 2-stage ring --------
// Interleaved softmax+PV per kc (no tensor-idle phase); 8 barriers per CTA.
#define AT2_STB  36864                  // stage: 128 K-rows (18432) + 128 V-rows
#define AT2_VOFF 18432
#define AT2_QOFF 73728                  // after 2 stages
#define ASM_TOTAL (AT2_QOFF + 128*144)  // 92160

__global__ __launch_bounds__(256, 2) void attn_kernel(
    const __half* __restrict__ qkv, __half* __restrict__ ctx)
{
    extern __shared__ char ash[];
    uint32_t sb = smem_u32(ash);
    int bh = blockIdx.y;
    int b  = bh >> 4, h = bh & 15;
    int qt = blockIdx.x;
    int tid = threadIdx.x, w = tid >> 5, lane = tid & 31, g = lane >> 2, t = lane & 3;
    int rb = w * 16;

    const __half* qp = qkv + (size_t)(b * S_ + qt * 128) * 3072 + h * 64;
    const __half* kp = qkv + (size_t)(b * S_) * 3072 + E_ + h * 64;
    const __half* vp = kp + E_;

    int rc = tid >> 3;        // staging row base (0..31), +u*32 -> 128 rows
    int qc = tid & 7;         // staging 16B-chunk within row

    // prologue: stage 0 (128 K rows + 128 V rows)
    {
        uint32_t kdst = sb + rc * 144 + qc * 16;
        #pragma unroll
        for (int u = 0; u < 4; u++) {
            cp_async16(kdst + u * 32 * 144,            kp + (size_t)(rc + u * 32) * 3072 + qc * 8);
            cp_async16(kdst + u * 32 * 144 + AT2_VOFF, vp + (size_t)(rc + u * 32) * 3072 + qc * 8);
        }
        asm volatile("cp.async.commit_group;\n");
    }

    // stage Q (scaled by 1/sqrt(D)*log2e), then pull fragments
    {
        __half* Qs = (__half*)(ash + AT2_QOFF);
        const float qsc = 0.125f * 1.4426950408889634f;
        #pragma unroll
        for (int u = 0; u < 4; u++) {
            int r = rc + u * 32;
            uint4 uq = *(const uint4*)(qp + (size_t)r * 3072 + qc * 8);
            __half2* hp = (__half2*)&uq;
            __half2 oq[4];
            #pragma unroll
            for (int j = 0; j < 4; j++) {
                float2 v = __half22float2(hp[j]);
                oq[j] = __floats2half2_rn(v.x * qsc, v.y * qsc);
            }
            *(uint4*)(Qs + r * 72 + qc * 8) = *(uint4*)oq;
        }
    }
    __syncthreads();
    unsigned qf[4][4];
    {
        uint32_t qbase = sb + AT2_QOFF + (rb + (lane & 15)) * 144 + (lane >> 4) * 16;
        #pragma unroll
        for (int kc = 0; kc < 4; kc++)
            ldsm_x4(qf[kc][0], qf[kc][1], qf[kc][2], qf[kc][3], qbase + kc * 32);
    }

    float o[8][4];
    #pragma unroll
    for (int i = 0; i < 8; i++)
        #pragma unroll
        for (int j = 0; j < 4; j++) o[i][j] = 0.f;
    float lacc[4] = {0.f, 0.f, 0.f, 0.f};
    const unsigned bones[2] = {0x3C003C00u, 0x3C003C00u};

    uint32_t kfb_rel = ((lane & 7) + ((lane >> 4) << 3)) * 144 + ((lane >> 3) & 1) * 16;
    uint32_t vfb_rel = (lane & 15) * 144 + (lane >> 4) * 16;

    int buf = 0;
    for (int it = 0; it < 8; it++) {
        asm volatile("cp.async.wait_group 0;\n");
        __syncthreads();

        // prefetch next 128-row K/V tile into the other buffer
        if (it + 1 < 8) {
            const __half* kb = kp + (size_t)(it + 1) * 128 * 3072;
            const __half* vb = vp + (size_t)(it + 1) * 128 * 3072;
            uint32_t kdst = sb + (buf ^ 1) * AT2_STB + rc * 144 + qc * 16;
            #pragma unroll
            for (int u = 0; u < 4; u++) {
                cp_async16(kdst + u * 32 * 144,            kb + (size_t)(rc + u * 32) * 3072 + qc * 8);
                cp_async16(kdst + u * 32 * 144 + AT2_VOFF, vb + (size_t)(rc + u * 32) * 3072 + qc * 8);
            }
        }
        asm volatile("cp.async.commit_group;\n");

        #pragma unroll
        for (int sub = 0; sub < 2; sub++) {
            uint32_t kb0 = sb + buf * AT2_STB + sub * (64 * 144) + kfb_rel;
            uint32_t vb0 = sb + buf * AT2_STB + AT2_VOFF + sub * (64 * 144) + vfb_rel;

            // ---- S = Q @ K^T (warp: 16 x 64) ----
            float s[8][4];
            #pragma unroll
            for (int i = 0; i < 8; i++)
                #pragma unroll
                for (int j = 0; j < 4; j++) s[i][j] = 0.f;
            #pragma unroll
            for (int kc = 0; kc < 4; kc++) {
                unsigned bf[8][2];
                #pragma unroll
                for (int p = 0; p < 4; p++) {
                    unsigned r0, r1, r2, r3;
                    ldsm_x4(r0, r1, r2, r3, kb0 + p * (16 * 144) + kc * 32);
                    bf[2*p][0] = r0; bf[2*p][1] = r1;
                    bf[2*p+1][0] = r2; bf[2*p+1][1] = r3;
                }
                #pragma unroll
                for (int nf = 0; nf < 8; nf++) mma_f16(s[nf], qf[kc], bf[nf]);
            }

            // ---- interleaved softmax + PV (per kc), incremental l pre-sum ----
            unsigned asum[4];
            #pragma unroll
            for (int kc = 0; kc < 4; kc++) {
                unsigned af[4];
                af[0] = ex2_h2(pack_h2(s[2*kc  ][0], s[2*kc  ][1]));
                af[1] = ex2_h2(pack_h2(s[2*kc  ][2], s[2*kc  ][3]));
                af[2] = ex2_h2(pack_h2(s[2*kc+1][0], s[2*kc+1][1]));
                af[3] = ex2_h2(pack_h2(s[2*kc+1][2], s[2*kc+1][3]));
                if (kc == 0) {
                    asum[0] = af[0]; asum[1] = af[1]; asum[2] = af[2]; asum[3] = af[3];
                } else {
                    asum[0] = hadd2u(asum[0], af[0]);
                    asum[1] = hadd2u(asum[1], af[1]);
                    asum[2] = hadd2u(asum[2], af[2]);
                    asum[3] = hadd2u(asum[3], af[3]);
                }
                #pragma unroll
                for (int dt = 0; dt < 4; dt++) {
                    unsigned r0, r1, r2, r3;
                    ldsm_x4_t(r0, r1, r2, r3, vb0 + kc * (16 * 144) + dt * 32);
                    unsigned bv0[2] = {r0, r1}, bv1[2] = {r2, r3};
                    mma_f16(o[2*dt],     af, bv0);
                    mma_f16(o[2*dt + 1], af, bv1);
                }
            }
            mma_f16(lacc, asum, bones);
        }
        buf ^= 1;
    }

    // every lane of the quad holds its row's full sum (all n-cols equal)
    float il0 = 1.0f / lacc[0], il1 = 1.0f / lacc[2];
    int r0 = qt * 128 + rb + g;
    __half* cb = ctx + (size_t)(b * S_) * E_ + h * 64;
    #pragma unroll
    for (int nf = 0; nf < 8; nf++) {
        int c0 = nf * 8 + 2 * t;
        *(__half2*)(cb + (size_t)r0 * E_ + c0) =
            __floats2half2_rn(o[nf][0] * il0, o[nf][1] * il0);
        *(__half2*)(cb + (size_t)(r0 + 8) * E_ + c0) =
            __floats2half2_rn(o[nf][2] * il1, o[nf][3] * il1);
    }
}

// ---------------- host launcher ----------------
extern "C" void kernel_launch(void* const* d_in, const int* in_sizes, int n_in,
                              void* d_out, int out_size)
{
    (void)in_sizes; (void)n_in; (void)out_size;
    const float* x     = (const float*)d_in[0];
    const float* in_w  = (const float*)d_in[1];
    const float* in_b  = (const float*)d_in[2];
    const float* out_w = (const float*)d_in[3];
    const float* out_b = (const float*)d_in[4];
    const float* l1w   = (const float*)d_in[5];
    const float* l1b   = (const float*)d_in[6];
    const float* l2w   = (const float*)d_in[7];
    const float* l2b   = (const float*)d_in[8];
    const float* n1w   = (const float*)d_in[9];
    const float* n1b   = (const float*)d_in[10];
    const float* n2w   = (const float*)d_in[11];
    const float* n2b   = (const float*)d_in[12];
    float* out = (float*)d_out;

    __half *xn, *qkvb, *ctx, *hb, *wbuf;
    float *x1;
    cudaGetSymbolAddress((void**)&xn,   g_xn);
    cudaGetSymbolAddress((void**)&qkvb, g_qkv);
    cudaGetSymbolAddress((void**)&ctx,  g_ctx);
    cudaGetSymbolAddress((void**)&x1,   g_x1);
    cudaGetSymbolAddress((void**)&hb,   g_h);
    cudaGetSymbolAddress((void**)&wbuf, g_w);

    cudaFuncSetAttribute(gemm_h<0>, cudaFuncAttributeMaxDynamicSharedMemorySize, GSM);
    cudaFuncSetAttribute(gemm_h<1>, cudaFuncAttributeMaxDynamicSharedMemorySize, GSM);
    cudaFuncSetAttribute(gemm_h<2>, cudaFuncAttributeMaxDynamicSharedMemorySize, GSM);
    cudaFuncSetAttribute(attn_kernel, cudaFuncAttributeMaxDynamicSharedMemorySize, ASM_TOTAL);

    // 0. convert all weights to fp16 (one fused kernel)
    cvt_all<<<6144, 256>>>(in_w, out_w, l1w, l2w, wbuf);

    // 1. xn = LN1(x)  (fp16, warp-per-row)
    ln_kernel<<<M_ / 8, 256>>>(x, n1w, n1b, xn);
    // 2. qkv = xn @ in_proj_w^T + in_proj_b   [16384, 3072] (fp16, persistent)
    gemm_h<0><<<NPERS, 256, GSM>>>(xn, wbuf + WOFF_IN, in_b, nullptr, qkvb,
                                   3 * E_, E_, (3 * E_ / 128) * (M_ / 128));
    // 3. ctx = flash-attention(qkv)  (fp16)
    attn_kernel<<<dim3(S_ / 128, B_ * H_), 256, ASM_TOTAL>>>(qkvb, ctx);
    // 4. x1 = x + ctx @ out_w^T + out_b  (fp32, persistent)
    gemm_h<2><<<NPERS, 256, GSM>>>(ctx, wbuf + WOFF_OUT, out_b, x, x1,
                                   E_, E_, (E_ / 128) * (M_ / 128));
    // 5. xn = LN2(x1)  (fp16, warp-per-row)
    ln_kernel<<<M_ / 8, 256>>>(x1, n2w, n2b, xn);
    // 6. h = gelu(xn @ lin1_w^T + lin1_b)     [16384, 4096] (fp16, persistent)
    gemm_h<1><<<NPERS, 256, GSM>>>(xn, wbuf + WOFF_L1, l1b, nullptr, hb,
                                   F_, E_, (F_ / 128) * (M_ / 128));
    // 7. out = x1 + h @ lin2_w^T + lin2_b  (fp32, persistent)
    gemm_h<2><<<NPERS, 256, GSM>>>(hb, wbuf + WOFF_L2, l2b, x1, out,
                                   E_, F_, (E_ / 128) * (M_ / 128));
}

// round 16
// speedup vs baseline: 1.0035x; 1.0035x over previous
#include <cuda_runtime.h>
#include <cuda_fp16.h>
#include <math.h>
#include <stdint.h>

#define B_  16
#define S_  1024
#define E_  1024
#define F_  4096
#define H_  16
#define D_  64
#define M_  (B_*S_)   // 16384 rows

// ---------------- scratch (device globals: allocation-free) ----------------
__device__ __half g_xn [(size_t)M_*E_];     //  32 MB  layernorm output (fp16)
__device__ __half g_qkv[(size_t)M_*3*E_];   //  96 MB  qkv projection (fp16)
__device__ __half g_ctx[(size_t)M_*E_];     //  32 MB  attention context (fp16)
__device__ __half g_x1 [(size_t)M_*E_];     //  32 MB  post-attention residual (fp16)
__device__ __half g_h  [(size_t)M_*F_];     // 128 MB  ffn hidden (fp16)
__device__ __half g_w  [12582912];          //  24 MB  fp16 weights

#define WOFF_IN   0
#define WOFF_OUT  3145728
#define WOFF_L1   4194304
#define WOFF_L2   8388608

// ---------------- helpers ----------------
__device__ __forceinline__ void mma_f16(float c[4], const unsigned a[4], const unsigned b[2]) {
    asm volatile(
        "mma.sync.aligned.m16n8k16.row.col.f32.f16.f16.f32 "
        "{%0,%1,%2,%3}, {%4,%5,%6,%7}, {%8,%9}, {%0,%1,%2,%3};\n"
        : "+f"(c[0]), "+f"(c[1]), "+f"(c[2]), "+f"(c[3])
        : "r"(a[0]), "r"(a[1]), "r"(a[2]), "r"(a[3]), "r"(b[0]), "r"(b[1]));
}
__device__ __forceinline__ void ldsm_x4(unsigned &r0, unsigned &r1, unsigned &r2, unsigned &r3, uint32_t a) {
    asm volatile("ldmatrix.sync.aligned.m8n8.x4.shared.b16 {%0,%1,%2,%3}, [%4];"
                 : "=r"(r0), "=r"(r1), "=r"(r2), "=r"(r3) : "r"(a));
}
__device__ __forceinline__ void ldsm_x4_t(unsigned &r0, unsigned &r1, unsigned &r2, unsigned &r3, uint32_t a) {
    asm volatile("ldmatrix.sync.aligned.m8n8.x4.trans.shared.b16 {%0,%1,%2,%3}, [%4];"
                 : "=r"(r0), "=r"(r1), "=r"(r2), "=r"(r3) : "r"(a));
}
__device__ __forceinline__ uint32_t smem_u32(const void* p) {
    uint32_t a;
    asm("{ .reg .u64 t; cvta.to.shared.u64 t, %1; cvt.u32.u64 %0, t; }" : "=r"(a) : "l"(p));
    return a;
}
__device__ __forceinline__ void cp_async16(unsigned dst, const void* src) {
    asm volatile("cp.async.cg.shared.global [%0], [%1], 16;\n" :: "r"(dst), "l"(src));
}
__device__ __forceinline__ unsigned pack_h2(float a, float b) {
    __half2 h = __floats2half2_rn(a, b);
    return *(unsigned*)&h;
}
__device__ __forceinline__ unsigned ex2_h2(unsigned x) {
    unsigned y;
    asm("ex2.approx.f16x2 %0, %1;" : "=r"(y) : "r"(x));
    return y;
}
__device__ __forceinline__ unsigned hadd2u(unsigned a, unsigned b) {
    __half2 r = __hadd2(*(__half2*)&a, *(__half2*)&b);
    return *(unsigned*)&r;
}
__device__ __forceinline__ float tanhf_apx(float x) {
    float y;
    asm("tanh.approx.f32 %0, %1;" : "=f"(y) : "f"(x));
    return y;
}
__device__ __forceinline__ float gelu_f(float x) {
    float inner = 0.7978845608028654f * (x + 0.044715f * x * x * x);
    return 0.5f * x * (1.0f + tanhf_apx(inner));
}

// ---------------- fused fp32 -> fp16 weight convert (all 4 weights) ---------
__global__ __launch_bounds__(256) void cvt_all(
    const float* __restrict__ s0, const float* __restrict__ s1,
    const float* __restrict__ s2, const float* __restrict__ s3,
    __half* __restrict__ dst)
{
    int c = blockIdx.x * 256 + threadIdx.x;   // chunk of 8 elements
    const float* src; size_t off;
    if (c < 393216)       { src = s0; off = (size_t)c * 8; }
    else if (c < 524288)  { src = s1; off = (size_t)(c - 393216) * 8; }
    else if (c < 1048576) { src = s2; off = (size_t)(c - 524288) * 8; }
    else                  { src = s3; off = (size_t)(c - 1048576) * 8; }
    float4 a = *(const float4*)(src + off);
    float4 b = *(const float4*)(src + off + 4);
    __half2 h[4];
    h[0] = __floats2half2_rn(a.x, a.y);
    h[1] = __floats2half2_rn(a.z, a.w);
    h[2] = __floats2half2_rn(b.x, b.y);
    h[3] = __floats2half2_rn(b.z, b.w);
    ((uint4*)dst)[c] = *(uint4*)h;
}

// ---------------- layernorm (fp32 input): warp-per-row, 8 rows/block --------
__global__ __launch_bounds__(256) void ln_kernel(
    const float* __restrict__ x, const float* __restrict__ w,
    const float* __restrict__ b, __half* __restrict__ y)
{
    int warp = threadIdx.x >> 5, lane = threadIdx.x & 31;
    int row  = blockIdx.x * 8 + warp;
    const float4* xr = (const float4*)(x + (size_t)row * E_);

    float4 v[8];
    #pragma unroll
    for (int i = 0; i < 8; i++) v[i] = xr[lane + i * 32];

    float s = 0.f, q = 0.f;
    #pragma unroll
    for (int i = 0; i < 8; i++) {
        s += v[i].x + v[i].y + v[i].z + v[i].w;
        q += v[i].x*v[i].x + v[i].y*v[i].y + v[i].z*v[i].z + v[i].w*v[i].w;
    }
    #pragma unroll
    for (int o = 16; o; o >>= 1) {
        s += __shfl_xor_sync(0xffffffffu, s, o);
        q += __shfl_xor_sync(0xffffffffu, q, o);
    }
    float mu  = s * (1.0f / E_);
    float var = q * (1.0f / E_) - mu * mu;
    float inv = rsqrtf(var + 1e-5f);

    uint4* yr = (uint4*)(y + (size_t)row * E_);
    #pragma unroll
    for (int i = 0; i < 8; i += 2) {
        float4 wv0 = ((const float4*)w)[lane + i * 32];
        float4 bv0 = ((const float4*)b)[lane + i * 32];
        float4 wv1 = ((const float4*)w)[lane + (i + 1) * 32];
        float4 bv1 = ((const float4*)b)[lane + (i + 1) * 32];
        __half2 h0 = __floats2half2_rn((v[i].x - mu) * inv * wv0.x + bv0.x,
                                       (v[i].y - mu) * inv * wv0.y + bv0.y);
        __half2 h1 = __floats2half2_rn((v[i].z - mu) * inv * wv0.z + bv0.z,
                                       (v[i].w - mu) * inv * wv0.w + bv0.w);
        __half2 h2 = __floats2half2_rn((v[i+1].x - mu) * inv * wv1.x + bv1.x,
                                       (v[i+1].y - mu) * inv * wv1.y + bv1.y);
        __half2 h3 = __floats2half2_rn((v[i+1].z - mu) * inv * wv1.z + bv1.z,
                                       (v[i+1].w - mu) * inv * wv1.w + bv1.w);
        uint2 u0; u0.x = *(unsigned*)&h0; u0.y = *(unsigned*)&h1;
        uint2 u1; u1.x = *(unsigned*)&h2; u1.y = *(unsigned*)&h3;
        ((uint2*)yr)[lane + i * 32]       = u0;
        ((uint2*)yr)[lane + (i + 1) * 32] = u1;
    }
}

// ---------------- layernorm (fp16 input): warp-per-row, 8 rows/block --------
__global__ __launch_bounds__(256) void ln_h(
    const __half* __restrict__ x, const float* __restrict__ w,
    const float* __restrict__ b, __half* __restrict__ y)
{
    int warp = threadIdx.x >> 5, lane = threadIdx.x & 31;
    int row  = blockIdx.x * 8 + warp;
    const uint4* xr = (const uint4*)(x + (size_t)row * E_);   // 128 uint4/row

    uint4 u[4];
    #pragma unroll
    for (int i = 0; i < 4; i++) u[i] = xr[lane + i * 32];

    float v[32];
    #pragma unroll
    for (int i = 0; i < 4; i++) {
        const __half2* hp = (const __half2*)&u[i];
        #pragma unroll
        for (int j = 0; j < 4; j++) {
            float2 f = __half22float2(hp[j]);
            v[i * 8 + 2*j]     = f.x;
            v[i * 8 + 2*j + 1] = f.y;
        }
    }

    float s = 0.f, q = 0.f;
    #pragma unroll
    for (int i = 0; i < 32; i++) { s += v[i]; q += v[i] * v[i]; }
    #pragma unroll
    for (int o = 16; o; o >>= 1) {
        s += __shfl_xor_sync(0xffffffffu, s, o);
        q += __shfl_xor_sync(0xffffffffu, q, o);
    }
    float mu  = s * (1.0f / E_);
    float var = q * (1.0f / E_) - mu * mu;
    float inv = rsqrtf(var + 1e-5f);

    uint4* yr = (uint4*)(y + (size_t)row * E_);
    #pragma unroll
    for (int i = 0; i < 4; i++) {
        // 8 elements of this chunk start at column (lane + i*32)*8
        int col = (lane + i * 32) * 8;
        __half2 h[4];
        #pragma unroll
        for (int j = 0; j < 4; j++) {
            float2 wv = *(const float2*)(w + col + 2*j);
            float2 bv = *(const float2*)(b + col + 2*j);
            h[j] = __floats2half2_rn((v[i*8 + 2*j]     - mu) * inv * wv.x + bv.x,
                                     (v[i*8 + 2*j + 1] - mu) * inv * wv.y + bv.y);
        }
        yr[lane + i * 32] = *(uint4*)h;
    }
}

// ---------------- persistent fp16 NT GEMM: C = A @ B^T (+bias, epi) ---------
// EPI: 0 = bias -> half            1 = bias + gelu(tanh) -> half
//      2 = bias + res(f32) -> half 3 = bias + res(f16) -> float
#define RSB   144                 // row stride bytes (128B data + 16B pad)
#define ABYT  (128*RSB)           // 18432 bytes per tile
#define STB   (2*ABYT)            // 36864 bytes per stage
#define NST   3
#define GSM   (NST*STB)           // 110592 bytes
#define NPERS 304                 // 2 CTAs x 152 SMs

template<int EPI>
__global__ __launch_bounds__(256, 2) void gemm_h(
    const __half* __restrict__ A, const __half* __restrict__ Bm,
    const float* __restrict__ bias, const void* __restrict__ resv,
    void* __restrict__ Cv, int N, int K, int ntiles)
{
    extern __shared__ char smh[];
    uint32_t sb = smem_u32(smh);
    int tid = threadIdx.x;
    int w = tid >> 5, lane = tid & 31, g = lane >> 2, t = lane & 3;
    int wm = (w >> 1) * 32, wn = (w & 1) * 64;
    int srow = tid >> 3, sq = tid & 7;
    uint32_t sA = srow * RSB + sq * 16;
    uint32_t sB = ABYT + sA;
    int arow = lane & 15;
    int akof = (lane >> 4) * 16;
    int brow = (lane & 7) + ((lane >> 4) << 3);
    int bkof = ((lane >> 3) & 1) * 16;
    int NT = N >> 7;
    int KT = K / 64;

    for (int tile = blockIdx.x; tile < ntiles; tile += NPERS) {
        int bn = (tile % NT) << 7;
        int bm = (tile / NT) << 7;
        const __half* gA = A  + (size_t)(bm + srow) * K + sq * 8;
        const __half* gB = Bm + (size_t)(bn + srow) * K + sq * 8;

        asm volatile("cp.async.wait_group 0;\n");
        __syncthreads();

        #pragma unroll
        for (int s = 0; s < 2; s++) {
            uint32_t stb = sb + s * STB;
            #pragma unroll
            for (int u = 0; u < 4; u++) {
                cp_async16(stb + sA + u * 32 * RSB, gA + (size_t)u * 32 * K + s * 64);
                cp_async16(stb + sB + u * 32 * RSB, gB + (size_t)u * 32 * K + s * 64);
            }
            asm volatile("cp.async.commit_group;\n");
        }

        float acc[2][8][4];
        #pragma unroll
        for (int i = 0; i < 2; i++)
            #pragma unroll
            for (int j = 0; j < 8; j++)
                #pragma unroll
                for (int k = 0; k < 4; k++) acc[i][j][k] = 0.f;

        int buf = 0;
        for (int kt = 0; kt < KT; kt++) {
            asm volatile("cp.async.wait_group 1;\n");
            __syncthreads();

            bool pf = (kt + 2 < KT);
            int nb = buf + 2; if (nb >= NST) nb -= NST;
            uint32_t stb = sb + nb * STB;
            int k0 = (kt + 2) * 64;

            uint32_t abase = sb + buf * STB + (wm + arow) * RSB + akof;
            uint32_t bbase = sb + buf * STB + ABYT + (wn + brow) * RSB + bkof;

            #pragma unroll
            for (int ks = 0; ks < 4; ks++) {
                if (pf) {
                    cp_async16(stb + sA + ks * 32 * RSB, gA + (size_t)ks * 32 * K + k0);
                    cp_async16(stb + sB + ks * 32 * RSB, gB + (size_t)ks * 32 * K + k0);
                }
                unsigned af[2][4], bf[8][2];
                #pragma unroll
                for (int mf = 0; mf < 2; mf++)
                    ldsm_x4(af[mf][0], af[mf][1], af[mf][2], af[mf][3],
                            abase + mf * 16 * RSB + ks * 32);
                #pragma unroll
                for (int p = 0; p < 4; p++) {
                    unsigned r0, r1, r2, r3;
                    ldsm_x4(r0, r1, r2, r3, bbase + p * 16 * RSB + ks * 32);
                    bf[2*p][0] = r0; bf[2*p][1] = r1;
                    bf[2*p+1][0] = r2; bf[2*p+1][1] = r3;
                }
                #pragma unroll
                for (int mf = 0; mf < 2; mf++)
                    #pragma unroll
                    for (int nf = 0; nf < 8; nf++)
                        mma_f16(acc[mf][nf], af[mf], bf[nf]);
            }
            asm volatile("cp.async.commit_group;\n");
            if (++buf == NST) buf = 0;
        }

        #pragma unroll
        for (int mf = 0; mf < 2; mf++) {
            size_t r0 = (size_t)(bm + wm + mf * 16 + g);
            float2 rs0[8], rs1[8];
            if (EPI == 2) {
                const float* res = (const float*)resv;
                #pragma unroll
                for (int nf = 0; nf < 8; nf++) {
                    int c0 = bn + wn + nf * 8 + 2 * t;
                    rs0[nf] = *(const float2*)(res + r0 * N + c0);
                    rs1[nf] = *(const float2*)(res + (r0 + 8) * N + c0);
                }
            }
            if (EPI == 3) {
                const __half* res = (const __half*)resv;
                #pragma unroll
                for (int nf = 0; nf < 8; nf++) {
                    int c0 = bn + wn + nf * 8 + 2 * t;
                    rs0[nf] = __half22float2(*(const __half2*)(res + r0 * N + c0));
                    rs1[nf] = __half22float2(*(const __half2*)(res + (r0 + 8) * N + c0));
                }
            }
            #pragma unroll
            for (int nf = 0; nf < 8; nf++) {
                int c0 = bn + wn + nf * 8 + 2 * t;
                float b0 = bias[c0], b1 = bias[c0 + 1];
                float v0 = acc[mf][nf][0] + b0;
                float v1 = acc[mf][nf][1] + b1;
                float v2 = acc[mf][nf][2] + b0;
                float v3 = acc[mf][nf][3] + b1;
                if (EPI == 1) {
                    v0 = gelu_f(v0);
                    v1 = gelu_f(v1);
                    v2 = gelu_f(v2);
                    v3 = gelu_f(v3);
                }
                if (EPI == 2 || EPI == 3) {
                    v0 += rs0[nf].x; v1 += rs0[nf].y;
                    v2 += rs1[nf].x; v3 += rs1[nf].y;
                }
                if (EPI == 3) {
                    float* C = (float*)Cv;
                    float2 o01; o01.x = v0; o01.y = v1;
                    float2 o23; o23.x = v2; o23.y = v3;
                    *(float2*)(C + r0 * N + c0)       = o01;
                    *(float2*)(C + (r0 + 8) * N + c0) = o23;
                } else {
                    __half* C = (__half*)Cv;
                    *(__half2*)(C + r0 * N + c0)       = __floats2half2_rn(v0, v1);
                    *(__half2*)(C + (r0 + 8) * N + c0) = __floats2half2_rn(v2, v3);
                }
            }
        }
    }
}

// ---------------- fp16 flash attention (R14 proven: 3-stage, kv-tile 64) ----
#define AT_STRIDE 9216                  // one K or V stage: 64 rows * 144 B
#define AV_OFF    (3*AT_STRIDE)         // 27648
#define AQ_OFF    (6*AT_STRIDE)         // 55296
#define ASM_TOTAL (AQ_OFF + 128*144)    // 73728

__global__ __launch_bounds__(256, 2) void attn_kernel(
    const __half* __restrict__ qkv, __half* __restrict__ ctx)
{
    extern __shared__ char ash[];
    uint32_t sb = smem_u32(ash);
    int bh = blockIdx.y;
    int b  = bh >> 4, h = bh & 15;
    int qt = blockIdx.x;
    int tid = threadIdx.x, w = tid >> 5, lane = tid & 31, g = lane >> 2, t = lane & 3;
    int rb = w * 16;

    const __half* qp = qkv + (size_t)(b * S_ + qt * 128) * 3072 + h * 64;
    const __half* kp = qkv + (size_t)(b * S_) * 3072 + E_ + h * 64;
    const __half* vp = kp + E_;

    int rc = tid >> 3;        // staging row base (0..31), +u*32
    int qc = tid & 7;         // staging 16B-chunk within row

    #pragma unroll
    for (int s = 0; s < 2; s++) {
        const __half* kb = kp + (size_t)s * 64 * 3072;
        const __half* vb = vp + (size_t)s * 64 * 3072;
        uint32_t kdst = sb + s * AT_STRIDE + rc * 144 + qc * 16;
        #pragma unroll
        for (int u = 0; u < 2; u++) {
            cp_async16(kdst + u * 32 * 144,          kb + (size_t)(rc + u * 32) * 3072 + qc * 8);
            cp_async16(kdst + u * 32 * 144 + AV_OFF, vb + (size_t)(rc + u * 32) * 3072 + qc * 8);
        }
        asm volatile("cp.async.commit_group;\n");
    }

    {
        __half* Qs = (__half*)(ash + AQ_OFF);
        const float qsc = 0.125f * 1.4426950408889634f;
        #pragma unroll
        for (int u = 0; u < 4; u++) {
            int r = rc + u * 32;
            uint4 uq = *(const uint4*)(qp + (size_t)r * 3072 + qc * 8);
            __half2* hp = (__half2*)&uq;
            __half2 oq[4];
            #pragma unroll
            for (int j = 0; j < 4; j++) {
                float2 v = __half22float2(hp[j]);
                oq[j] = __floats2half2_rn(v.x * qsc, v.y * qsc);
            }
            *(uint4*)(Qs + r * 72 + qc * 8) = *(uint4*)oq;
        }
    }
    __syncthreads();
    unsigned qf[4][4];
    {
        uint32_t qbase = sb + AQ_OFF + (rb + (lane & 15)) * 144 + (lane >> 4) * 16;
        #pragma unroll
        for (int kc = 0; kc < 4; kc++)
            ldsm_x4(qf[kc][0], qf[kc][1], qf[kc][2], qf[kc][3], qbase + kc * 32);
    }

    float o[8][4];
    #pragma unroll
    for (int i = 0; i < 8; i++)
        #pragma unroll
        for (int j = 0; j < 4; j++) o[i][j] = 0.f;
    float lacc[4] = {0.f, 0.f, 0.f, 0.f};
    const unsigned bones[2] = {0x3C003C00u, 0x3C003C00u};

    uint32_t kfb = sb + ((lane & 7) + ((lane >> 4) << 3)) * 144 + ((lane >> 3) & 1) * 16;
    uint32_t vfb = sb + AV_OFF + (lane & 15) * 144 + (lane >> 4) * 16;

    int buf = 0;
    for (int kt = 0; kt < 16; kt++) {
        asm volatile("cp.async.wait_group 1;\n");
        __syncthreads();

        bool pf = (kt + 2 < 16);
        int nb = buf + 2; if (nb >= 3) nb -= 3;
        const __half* kb = kp + (size_t)(kt + 2) * 64 * 3072;
        const __half* vb = vp + (size_t)(kt + 2) * 64 * 3072;
        uint32_t kdst = sb + nb * AT_STRIDE + rc * 144 + qc * 16;

        float s[8][4];
        #pragma unroll
        for (int i = 0; i < 8; i++)
            #pragma unroll
            for (int j = 0; j < 4; j++) s[i][j] = 0.f;
        uint32_t kb0 = kfb + buf * AT_STRIDE;
        #pragma unroll
        for (int kc = 0; kc < 4; kc++) {
            if (pf) {
                int u = kc & 1;
                if (kc < 2)
                    cp_async16(kdst + u * 32 * 144,          kb + (size_t)(rc + u * 32) * 3072 + qc * 8);
                else
                    cp_async16(kdst + u * 32 * 144 + AV_OFF, vb + (size_t)(rc + u * 32) * 3072 + qc * 8);
            }
            unsigned bf[8][2];
            #pragma unroll
            for (int p = 0; p < 4; p++) {
                unsigned r0, r1, r2, r3;
                ldsm_x4(r0, r1, r2, r3, kb0 + p * (16 * 144) + kc * 32);
                bf[2*p][0] = r0; bf[2*p][1] = r1;
                bf[2*p+1][0] = r2; bf[2*p+1][1] = r3;
            }
            #pragma unroll
            for (int nf = 0; nf < 8; nf++) mma_f16(s[nf], qf[kc], bf[nf]);
        }
        asm volatile("cp.async.commit_group;\n");

        unsigned pfr[8][2];
        #pragma unroll
        for (int nf = 0; nf < 8; nf++) {
            pfr[nf][0] = ex2_h2(pack_h2(s[nf][0], s[nf][1]));
            pfr[nf][1] = ex2_h2(pack_h2(s[nf][2], s[nf][3]));
        }

        {
            unsigned asum[4];
            asum[0] = hadd2u(hadd2u(pfr[0][0], pfr[2][0]), hadd2u(pfr[4][0], pfr[6][0]));
            asum[1] = hadd2u(hadd2u(pfr[0][1], pfr[2][1]), hadd2u(pfr[4][1], pfr[6][1]));
            asum[2] = hadd2u(hadd2u(pfr[1][0], pfr[3][0]), hadd2u(pfr[5][0], pfr[7][0]));
            asum[3] = hadd2u(hadd2u(pfr[1][1], pfr[3][1]), hadd2u(pfr[5][1], pfr[7][1]));
            mma_f16(lacc, asum, bones);
        }

        uint32_t vb0 = vfb + buf * AT_STRIDE;
        #pragma unroll
        for (int kc = 0; kc < 4; kc++) {
            unsigned af[4];
            af[0] = pfr[2*kc  ][0];
            af[1] = pfr[2*kc  ][1];
            af[2] = pfr[2*kc+1][0];
            af[3] = pfr[2*kc+1][1];
            #pragma unroll
            for (int dt = 0; dt < 4; dt++) {
                unsigned r0, r1, r2, r3;
                ldsm_x4_t(r0, r1, r2, r3, vb0 + kc * (16 * 144) + dt * 32);
                unsigned bv0[2] = {r0, r1}, bv1[2] = {r2, r3};
                mma_f16(o[2*dt],     af, bv0);
                mma_f16(o[2*dt + 1], af, bv1);
            }
        }

        if (++buf == 3) buf = 0;
    }

    float il0 = 1.0f / lacc[0], il1 = 1.0f / lacc[2];
    int r0 = qt * 128 + rb + g;
    __half* cb = ctx + (size_t)(b * S_) * E_ + h * 64;
    #pragma unroll
    for (int nf = 0; nf < 8; nf++) {
        int c0 = nf * 8 + 2 * t;
        *(__half2*)(cb + (size_t)r0 * E_ + c0) =
            __floats2half2_rn(o[nf][0] * il0, o[nf][1] * il0);
        *(__half2*)(cb + (size_t)(r0 + 8) * E_ + c0) =
            __floats2half2_rn(o[nf][2] * il1, o[nf][3] * il1);
    }
}

// ---------------- host launcher ----------------
extern "C" void kernel_launch(void* const* d_in, const int* in_sizes, int n_in,
                              void* d_out, int out_size)
{
    (void)in_sizes; (void)n_in; (void)out_size;
    const float* x     = (const float*)d_in[0];
    const float* in_w  = (const float*)d_in[1];
    const float* in_b  = (const float*)d_in[2];
    const float* out_w = (const float*)d_in[3];
    const float* out_b = (const float*)d_in[4];
    const float* l1w   = (const float*)d_in[5];
    const float* l1b   = (const float*)d_in[6];
    const float* l2w   = (const float*)d_in[7];
    const float* l2b   = (const float*)d_in[8];
    const float* n1w   = (const float*)d_in[9];
    const float* n1b   = (const float*)d_in[10];
    const float* n2w   = (const float*)d_in[11];
    const float* n2b   = (const float*)d_in[12];
    float* out = (float*)d_out;

    __half *xn, *qkvb, *ctx, *x1, *hb, *wbuf;
    cudaGetSymbolAddress((void**)&xn,   g_xn);
    cudaGetSymbolAddress((void**)&qkvb, g_qkv);
    cudaGetSymbolAddress((void**)&ctx,  g_ctx);
    cudaGetSymbolAddress((void**)&x1,   g_x1);
    cudaGetSymbolAddress((void**)&hb,   g_h);
    cudaGetSymbolAddress((void**)&wbuf, g_w);

    cudaFuncSetAttribute(gemm_h<0>, cudaFuncAttributeMaxDynamicSharedMemorySize, GSM);
    cudaFuncSetAttribute(gemm_h<1>, cudaFuncAttributeMaxDynamicSharedMemorySize, GSM);
    cudaFuncSetAttribute(gemm_h<2>, cudaFuncAttributeMaxDynamicSharedMemorySize, GSM);
    cudaFuncSetAttribute(gemm_h<3>, cudaFuncAttributeMaxDynamicSharedMemorySize, GSM);
    cudaFuncSetAttribute(attn_kernel, cudaFuncAttributeMaxDynamicSharedMemorySize, ASM_TOTAL);

    // 0. convert all weights to fp16 (one fused kernel)
    cvt_all<<<6144, 256>>>(in_w, out_w, l1w, l2w, wbuf);

    // 1. xn = LN1(x)  (fp16, warp-per-row)
    ln_kernel<<<M_ / 8, 256>>>(x, n1w, n1b, xn);
    // 2. qkv = xn @ in_proj_w^T + in_proj_b   [16384, 3072] (fp16, persistent)
    gemm_h<0><<<NPERS, 256, GSM>>>(xn, wbuf + WOFF_IN, in_b, nullptr, qkvb,
                                   3 * E_, E_, (3 * E_ / 128) * (M_ / 128));
    // 3. ctx = flash-attention(qkv)  (fp16)
    attn_kernel<<<dim3(S_ / 128, B_ * H_), 256, ASM_TOTAL>>>(qkvb, ctx);
    // 4. x1 = x + ctx @ out_w^T + out_b  (fp16 out, fp32 residual; persistent)
    gemm_h<2><<<NPERS, 256, GSM>>>(ctx, wbuf + WOFF_OUT, out_b, x, x1,
                                   E_, E_, (E_ / 128) * (M_ / 128));
    // 5. xn = LN2(x1)  (fp16 in/out, warp-per-row)
    ln_h<<<M_ / 8, 256>>>(x1, n2w, n2b, xn);
    // 6. h = gelu(xn @ lin1_w^T + lin1_b)     [16384, 4096] (fp16, persistent)
    gemm_h<1><<<NPERS, 256, GSM>>>(xn, wbuf + WOFF_L1, l1b, nullptr, hb,
                                   F_, E_, (F_ / 128) * (M_ / 128));
    // 7. out = x1 + h @ lin2_w^T + lin2_b  (fp32 out, fp16 residual; persistent)
    gemm_h<3><<<NPERS, 256, GSM>>>(hb, wbuf + WOFF_L2, l2b, x1, out,
                                   E_, F_, (E_ / 128) * (M_ / 128));
}